// round 5
// baseline (speedup 1.0000x reference)
#include <cuda_runtime.h>
#include <cuda_bf16.h>
#include <cstdint>

#define N_NODES 63
#define C_CLASSES 100
#define B_TOT 8192
#define D_DIM 512
#define NTN 4096

// ---------------- device scratch ----------------
__device__ __nv_bfloat16 g_xh[B_TOT * D_DIM], g_xl[B_TOT * D_DIM];
__device__ __nv_bfloat16 g_wh[NTN * D_DIM], g_wl[NTN * D_DIM];
__device__ __nv_bfloat16 g_m[128 * NTN];                    // rows >=100 stay zero
__device__ __nv_bfloat16 g_lp[(size_t)B_TOT * NTN];

// ---------------- helpers ----------------
__device__ __forceinline__ uint32_t s2u(const void* p) {
    uint32_t a;
    asm("{ .reg .u64 t; cvta.to.shared.u64 t, %1; cvt.u32.u64 %0, t; }" : "=r"(a) : "l"(p));
    return a;
}
#define CP_COMMIT() asm volatile("cp.async.commit_group;" ::: "memory")
#define CP_WAIT(n)  asm volatile("cp.async.wait_group %0;" :: "n"(n) : "memory")
__device__ __forceinline__ void cp16(uint32_t dst, const void* src) {
    asm volatile("cp.async.cg.shared.global [%0], [%1], 16;" :: "r"(dst), "l"(src) : "memory");
}
// generic staged tile (used by gemm2 only)
__device__ __forceinline__ void stage_tile(uint32_t dstBase, const char* src, size_t rowB, int nRows) {
    const int units = nRows * 8;
    for (int u = threadIdx.x; u < units; u += 256) {
        int r = u >> 3, cu = u & 7;
        cp16(dstBase + (uint32_t)(((r << 3) + (cu ^ (r & 7))) << 4), src + (size_t)r * rowB + (cu << 4));
    }
}

#define LDSM4(a, addr) asm volatile( \
    "ldmatrix.sync.aligned.m8n8.x4.shared.b16 {%0,%1,%2,%3}, [%4];" \
    : "=r"((a)[0]), "=r"((a)[1]), "=r"((a)[2]), "=r"((a)[3]) : "r"(addr))
#define LDSM2(b, addr) asm volatile( \
    "ldmatrix.sync.aligned.m8n8.x2.shared.b16 {%0,%1}, [%2];" \
    : "=r"((b)[0]), "=r"((b)[1]) : "r"(addr))
#define MMA(c, a, b0, b1) asm volatile( \
    "mma.sync.aligned.m16n8k16.row.col.f32.bf16.bf16.f32 " \
    "{%0,%1,%2,%3},{%4,%5,%6,%7},{%8,%9},{%0,%1,%2,%3};" \
    : "+f"((c)[0]), "+f"((c)[1]), "+f"((c)[2]), "+f"((c)[3]) \
    : "r"((a)[0]), "r"((a)[1]), "r"((a)[2]), "r"((a)[3]), "r"(b0), "r"(b1))

// ============ prep ============
__global__ void prep_x(const float* __restrict__ x) {
    int i = blockIdx.x * 256 + threadIdx.x;
    float v = x[i];
    __nv_bfloat16 h = __float2bfloat16(v);
    g_xh[i] = h;
    g_xl[i] = __float2bfloat16(v - __bfloat162float(h));
}
__global__ void prep_w(const float* __restrict__ W) {
    int i = blockIdx.x * 256 + threadIdx.x;
    int row = i >> 9, k = i & 511, t = row >> 6, n = row & 63;
    float v = (n < N_NODES) ? W[((size_t)t * N_NODES + n) * D_DIM + k] : 0.f;
    __nv_bfloat16 h = __float2bfloat16(v);
    g_wh[i] = h;
    g_wl[i] = __float2bfloat16(v - __bfloat162float(h));
}
__global__ void prep_m(const float* __restrict__ ll, const float* __restrict__ tw) {
    int row = blockIdx.x * 8 + (threadIdx.x >> 5);   // t*64 + l
    int lane = threadIdx.x & 31;
    const float* src = ll + (size_t)row * C_CLASSES;
    float v[4];
#pragma unroll
    for (int q = 0; q < 4; ++q) { int c = lane + 32 * q; v[q] = (c < C_CLASSES) ? src[c] : -1e30f; }
    float mx = fmaxf(fmaxf(v[0], v[1]), fmaxf(v[2], v[3]));
#pragma unroll
    for (int o = 16; o; o >>= 1) mx = fmaxf(mx, __shfl_xor_sync(~0u, mx, o));
    float e[4], s = 0.f;
#pragma unroll
    for (int q = 0; q < 4; ++q) { int c = lane + 32 * q; e[q] = (c < C_CLASSES) ? __expf(v[q] - mx) : 0.f; s += e[q]; }
#pragma unroll
    for (int o = 16; o; o >>= 1) s += __shfl_xor_sync(~0u, s, o);
    float scale = tw[row >> 6] / s;
#pragma unroll
    for (int q = 0; q < 4; ++q) {
        int c = lane + 32 * q;
        if (c < C_CLASSES) g_m[(size_t)c * NTN + row] = __float2bfloat16(e[q] * scale);
    }
}

// ============ GEMM1 + sigmoid + leaf product fused ============
// CTA tile 128(M batch) x 256(N = 4 trees). grid (64, 16). 8 warps (2M x 4N), warp 64x64.
#define G1_SOFF 2048
#define G1_ABUF 16384
#define G1_BUF  49152                       // A 16KB + B 32KB
#define G1_SMEM (G1_SOFF + 2 * G1_BUF)      // 100352

__global__ void __launch_bounds__(256) gemm1_kernel(const float* __restrict__ bias) {
    extern __shared__ char smem[];
    const uint32_t sb = s2u(smem);
    const int tid = threadIdx.x, wid = tid >> 5, lane = tid & 31;
    const int b0 = blockIdx.x * 128, ntb = blockIdx.y;

    if (tid < 252) {
        int tt = tid / 63, n = tid % 63;
        ((float*)(smem + 128))[tt * 64 + n] = bias[((ntb * 4 + tt)) * N_NODES + n];
    }

    const char* xh = (const char*)g_xh + (size_t)b0 * 1024;
    const char* xl = (const char*)g_xl + (size_t)b0 * 1024;
    const char* wh = (const char*)g_wh + (size_t)(ntb * 256) * 1024;
    const char* wl = (const char*)g_wl + (size_t)(ntb * 256) * 1024;
    const char* Asrc[3] = {xh, xl, xh};
    const char* Bsrc[3] = {wh, wh, wl};

    // hoisted staging geometry (fixed per thread across segments)
    const int sr = tid >> 3, scu = tid & 7;
    const uint32_t dst0 = (uint32_t)(((sr << 3) + (scu ^ (sr & 7))) << 4);  // + it*4096
    const size_t   src0 = (size_t)sr * 1024 + (scu << 4);                  // + it*32768

#define G1_SEG(seg) do { int _p = (seg) >> 3, _kc = (seg) & 7; \
    const char* _as = Asrc[_p] + _kc * 128; const char* _bs = Bsrc[_p] + _kc * 128; \
    uint32_t _d = sb + G1_SOFF + ((seg) & 1) * G1_BUF; \
    _Pragma("unroll") for (int _it = 0; _it < 4; ++_it) \
        cp16(_d + dst0 + _it * 4096, _as + src0 + (size_t)_it * 32768); \
    _d += G1_ABUF; \
    _Pragma("unroll") for (int _it = 0; _it < 8; ++_it) \
        cp16(_d + dst0 + _it * 4096, _bs + src0 + (size_t)_it * 32768); \
    CP_COMMIT(); } while (0)

    // per-warp MMA geometry
    const int wm = wid >> 2, wn = wid & 3;
    const int m0w = wm * 64, n0w = wn * 64;
    const uint32_t sx = lane & 7;
    const uint32_t aKh = (lane >> 4) & 1, bKh = (lane >> 3) & 1;
    uint32_t rA[4], rB[4];
#pragma unroll
    for (int mt = 0; mt < 4; ++mt) rA[mt] = (uint32_t)(m0w + mt * 16 + (lane & 15)) * 128;
#pragma unroll
    for (int np = 0; np < 4; ++np)
        rB[np] = (uint32_t)(n0w + np * 16 + (lane & 7) + ((lane & 16) >> 1)) * 128;

    float acc[4][8][4];
#pragma unroll
    for (int mt = 0; mt < 4; ++mt)
#pragma unroll
        for (int nf = 0; nf < 8; ++nf)
#pragma unroll
            for (int q = 0; q < 4; ++q) acc[mt][nf][q] = 0.f;

    G1_SEG(0); G1_SEG(1);
#pragma unroll 1
    for (int seg = 0; seg < 24; ++seg) {
        if (seg < 23) { CP_WAIT(1); } else { CP_WAIT(0); }
        __syncthreads();
        const uint32_t Ab = sb + G1_SOFF + (seg & 1) * G1_BUF;
        const uint32_t Bb = Ab + G1_ABUF;

        uint32_t a[2][4][4], bq[2][4][4];
        // prefetch ks=0
#pragma unroll
        for (int mt = 0; mt < 4; ++mt) LDSM4(a[0][mt], Ab + rA[mt] + ((aKh ^ sx) << 4));
#pragma unroll
        for (int np = 0; np < 4; ++np) LDSM4(bq[0][np], Bb + rB[np] + ((bKh ^ sx) << 4));

#pragma unroll
        for (int ks = 0; ks < 4; ++ks) {
            const int cur = ks & 1, nxt = cur ^ 1;
            if (ks < 3) {
                const uint32_t koA = (((uint32_t)(ks + 1) * 2 + aKh) ^ sx) << 4;
                const uint32_t koB = (((uint32_t)(ks + 1) * 2 + bKh) ^ sx) << 4;
#pragma unroll
                for (int mt = 0; mt < 4; ++mt) LDSM4(a[nxt][mt], Ab + rA[mt] + koA);
#pragma unroll
                for (int np = 0; np < 4; ++np) LDSM4(bq[nxt][np], Bb + rB[np] + koB);
            }
#pragma unroll
            for (int mt = 0; mt < 4; ++mt)
#pragma unroll
                for (int np = 0; np < 4; ++np) {
                    MMA(acc[mt][np * 2],     a[cur][mt], bq[cur][np][0], bq[cur][np][1]);
                    MMA(acc[mt][np * 2 + 1], a[cur][mt], bq[cur][np][2], bq[cur][np][3]);
                }
        }
        __syncthreads();
        if (seg + 2 < 24) G1_SEG(seg + 2);
    }

    // ---- epilogue in two 128-col halves (dec tile reuses stage smem) ----
    float* dec = (float*)(smem + G1_SOFF);        // 128 x pitch129 fp32
    const float* bsm = (const float*)(smem + 128);
    const int r4 = lane >> 2, c2 = (lane & 3) * 2;

#pragma unroll 1
    for (int h = 0; h < 2; ++h) {
        __syncthreads();
        if ((wn >> 1) == h) {
            const int colb = (wn & 1) * 64;
#pragma unroll
            for (int mt = 0; mt < 4; ++mt)
#pragma unroll
                for (int nf = 0; nf < 8; ++nf) {
                    int row = m0w + mt * 16 + r4, col = colb + nf * 8 + c2;
                    dec[row * 129 + col]           = acc[mt][nf][0];
                    dec[row * 129 + col + 1]       = acc[mt][nf][1];
                    dec[(row + 8) * 129 + col]     = acc[mt][nf][2];
                    dec[(row + 8) * 129 + col + 1] = acc[mt][nf][3];
                }
        }
        __syncthreads();
        {
            const int row = tid & 127, tt = tid >> 7;   // tree-in-half
            const int tree = h * 2 + tt;
            const float* dr = dec + row * 129 + tt * 64;
            const float* bs = bsm + tree * 64;
            float dc[63];
#pragma unroll
            for (int n = 0; n < 63; ++n)
                dc[n] = __fdividef(1.f, 1.f + __expf(-(dr[n] + bs[n])));
            float p[64];
            p[0] = 1.f;
#pragma unroll
            for (int d = 0; d < 6; ++d)
#pragma unroll
                for (int i = (1 << d) - 1; i >= 0; --i) {
                    float v = dc[(1 << d) - 1 + i], pi = p[i];
                    p[2 * i + 1] = pi * v;
                    p[2 * i]     = pi * (1.f - v);
                }
            __nv_bfloat16 ob[64];
#pragma unroll
            for (int l = 0; l < 64; ++l) ob[l] = __float2bfloat16(p[l]);
            uint4* dst = (uint4*)(g_lp + (size_t)(b0 + row) * NTN + ntb * 256 + tree * 64);
            const uint4* srcv = (const uint4*)ob;
#pragma unroll
            for (int q = 0; q < 8; ++q) dst[q] = srcv[q];
        }
    }
}

// ============ GEMM2: out[8192,100] = lp @ M^T ============
// grid 128: 64 batch rows x 128 classes (>=100 zero). 8 warps (2M x 4N), warp 32x32.
#define G2_SOFF 1024
#define G2_BUF  24576                       // A 8KB + B 16KB
#define G2_SMEM (G2_SOFF + 2 * G2_BUF)      // 50176

__global__ void __launch_bounds__(256) gemm2_kernel(float* __restrict__ out) {
    extern __shared__ char smem[];
    const uint32_t sb = s2u(smem);
    const int tid = threadIdx.x, wid = tid >> 5, lane = tid & 31;
    const int b0 = blockIdx.x * 64;

    const char* Ag = (const char*)g_lp + (size_t)b0 * 8192;
    const char* Bg = (const char*)g_m;

#define G2_SEG(seg) do { uint32_t _b = sb + G2_SOFF + ((seg) & 1) * G2_BUF; \
    stage_tile(_b, Ag + (size_t)(seg) * 128, 8192, 64); \
    stage_tile(_b + 8192, Bg + (size_t)(seg) * 128, 8192, 128); \
    CP_COMMIT(); } while (0)

    const int wm = wid >> 2, wn = wid & 3;
    const int m0w = wm * 32, n0w = wn * 32;
    const uint32_t sx = lane & 7;
    const uint32_t aKh = (lane >> 4) & 1, bKh = (lane >> 3) & 1;
    uint32_t rA[2], rB[4];
#pragma unroll
    for (int mt = 0; mt < 2; ++mt) rA[mt] = (uint32_t)(m0w + mt * 16 + (lane & 15)) * 128;
#pragma unroll
    for (int nt = 0; nt < 4; ++nt) rB[nt] = (uint32_t)(n0w + nt * 8 + (lane & 7)) * 128;

    float acc[2][4][4];
#pragma unroll
    for (int mt = 0; mt < 2; ++mt)
#pragma unroll
        for (int nt = 0; nt < 4; ++nt)
#pragma unroll
            for (int q = 0; q < 4; ++q) acc[mt][nt][q] = 0.f;

    G2_SEG(0); G2_SEG(1);
#pragma unroll 1
    for (int seg = 0; seg < 64; ++seg) {
        if (seg < 63) { CP_WAIT(1); } else { CP_WAIT(0); }
        __syncthreads();
        uint32_t Ab = sb + G2_SOFF + (seg & 1) * G2_BUF;
        uint32_t Bb = Ab + 8192;
#pragma unroll
        for (int ks = 0; ks < 4; ++ks) {
            uint32_t a[2][4], b[4][2];
#pragma unroll
            for (int mt = 0; mt < 2; ++mt)
                LDSM4(a[mt], Ab + rA[mt] + ((((uint32_t)ks * 2 + aKh) ^ sx) << 4));
#pragma unroll
            for (int nt = 0; nt < 4; ++nt)
                LDSM2(b[nt], Bb + rB[nt] + ((((uint32_t)ks * 2 + bKh) ^ sx) << 4));
#pragma unroll
            for (int mt = 0; mt < 2; ++mt)
#pragma unroll
                for (int nt = 0; nt < 4; ++nt)
                    MMA(acc[mt][nt], a[mt], b[nt][0], b[nt][1]);
        }
        __syncthreads();
        if (seg + 2 < 64) G2_SEG(seg + 2);
    }

    {
        const int r = lane >> 2, c2 = (lane & 3) * 2;
#pragma unroll
        for (int mt = 0; mt < 2; ++mt)
#pragma unroll
            for (int nt = 0; nt < 4; ++nt) {
                int row = b0 + m0w + mt * 16 + r;
                int col = n0w + nt * 8 + c2;
                if (col < C_CLASSES) {
                    out[(size_t)row * C_CLASSES + col]       = acc[mt][nt][0];
                    out[(size_t)(row + 8) * C_CLASSES + col] = acc[mt][nt][2];
                }
                if (col + 1 < C_CLASSES) {
                    out[(size_t)row * C_CLASSES + col + 1]       = acc[mt][nt][1];
                    out[(size_t)(row + 8) * C_CLASSES + col + 1] = acc[mt][nt][3];
                }
            }
    }
}

// ============ launch ============
extern "C" void kernel_launch(void* const* d_in, const int* in_sizes, int n_in,
                              void* d_out, int out_size) {
    const float* x    = (const float*)d_in[0];
    const float* W    = (const float*)d_in[1];
    const float* bias = (const float*)d_in[2];
    const float* ll   = (const float*)d_in[3];
    const float* tw   = (const float*)d_in[4];
    float* out = (float*)d_out;

    cudaFuncSetAttribute(gemm1_kernel, cudaFuncAttributeMaxDynamicSharedMemorySize, G1_SMEM);
    cudaFuncSetAttribute(gemm2_kernel, cudaFuncAttributeMaxDynamicSharedMemorySize, G2_SMEM);

    prep_x<<<B_TOT * D_DIM / 256, 256>>>(x);
    prep_w<<<NTN * D_DIM / 256, 256>>>(W);
    prep_m<<<512, 256>>>(ll, tw);
    gemm1_kernel<<<dim3(64, 16), 256, G1_SMEM>>>(bias);
    gemm2_kernel<<<128, 256, G2_SMEM>>>(out);
}

// round 6
// speedup vs baseline: 1.0184x; 1.0184x over previous
#include <cuda_runtime.h>
#include <cuda_bf16.h>
#include <cstdint>

#define N_NODES 63
#define C_CLASSES 100
#define B_TOT 8192
#define D_DIM 512
#define NTN 4096

// ---------------- device scratch ----------------
__device__ __nv_bfloat16 g_xh[B_TOT * D_DIM], g_xl[B_TOT * D_DIM];
__device__ __nv_bfloat16 g_wh[NTN * D_DIM], g_wl[NTN * D_DIM];
__device__ __nv_bfloat16 g_m[128 * NTN];                    // rows >=100 stay zero
__device__ __nv_bfloat16 g_lp[(size_t)B_TOT * NTN];
__device__ float g_part[4 * B_TOT * C_CLASSES];

// ---------------- helpers ----------------
__device__ __forceinline__ uint32_t s2u(const void* p) {
    uint32_t a;
    asm("{ .reg .u64 t; cvta.to.shared.u64 t, %1; cvt.u32.u64 %0, t; }" : "=r"(a) : "l"(p));
    return a;
}
#define CP_COMMIT() asm volatile("cp.async.commit_group;" ::: "memory")
#define CP_WAIT(n)  asm volatile("cp.async.wait_group %0;" :: "n"(n) : "memory")
__device__ __forceinline__ void cp16(uint32_t dst, const void* src) {
    asm volatile("cp.async.cg.shared.global [%0], [%1], 16;" :: "r"(dst), "l"(src) : "memory");
}
// generic staged tile (gemm2): 256 threads
__device__ __forceinline__ void stage_tile(uint32_t dstBase, const char* src, size_t rowB, int nRows) {
    const int units = nRows * 8;
    for (int u = threadIdx.x; u < units; u += 256) {
        int r = u >> 3, cu = u & 7;
        cp16(dstBase + (uint32_t)(((r << 3) + (cu ^ (r & 7))) << 4), src + (size_t)r * rowB + (cu << 4));
    }
}

#define LDSM4(a, addr) asm volatile( \
    "ldmatrix.sync.aligned.m8n8.x4.shared.b16 {%0,%1,%2,%3}, [%4];" \
    : "=r"((a)[0]), "=r"((a)[1]), "=r"((a)[2]), "=r"((a)[3]) : "r"(addr))
#define LDSM2(b, addr) asm volatile( \
    "ldmatrix.sync.aligned.m8n8.x2.shared.b16 {%0,%1}, [%2];" \
    : "=r"((b)[0]), "=r"((b)[1]) : "r"(addr))
#define MMA(c, a, b0, b1) asm volatile( \
    "mma.sync.aligned.m16n8k16.row.col.f32.bf16.bf16.f32 " \
    "{%0,%1,%2,%3},{%4,%5,%6,%7},{%8,%9},{%0,%1,%2,%3};" \
    : "+f"((c)[0]), "+f"((c)[1]), "+f"((c)[2]), "+f"((c)[3]) \
    : "r"((a)[0]), "r"((a)[1]), "r"((a)[2]), "r"((a)[3]), "r"(b0), "r"(b1))

// ============ prep ============
__global__ void prep_x(const float* __restrict__ x) {
    int i = blockIdx.x * 256 + threadIdx.x;
    float v = x[i];
    __nv_bfloat16 h = __float2bfloat16(v);
    g_xh[i] = h;
    g_xl[i] = __float2bfloat16(v - __bfloat162float(h));
}
__global__ void prep_w(const float* __restrict__ W) {
    int i = blockIdx.x * 256 + threadIdx.x;
    int row = i >> 9, k = i & 511, t = row >> 6, n = row & 63;
    float v = (n < N_NODES) ? W[((size_t)t * N_NODES + n) * D_DIM + k] : 0.f;
    __nv_bfloat16 h = __float2bfloat16(v);
    g_wh[i] = h;
    g_wl[i] = __float2bfloat16(v - __bfloat162float(h));
}
__global__ void prep_m(const float* __restrict__ ll, const float* __restrict__ tw) {
    int row = blockIdx.x * 8 + (threadIdx.x >> 5);   // t*64 + l
    int lane = threadIdx.x & 31;
    const float* src = ll + (size_t)row * C_CLASSES;
    float v[4];
#pragma unroll
    for (int q = 0; q < 4; ++q) { int c = lane + 32 * q; v[q] = (c < C_CLASSES) ? src[c] : -1e30f; }
    float mx = fmaxf(fmaxf(v[0], v[1]), fmaxf(v[2], v[3]));
#pragma unroll
    for (int o = 16; o; o >>= 1) mx = fmaxf(mx, __shfl_xor_sync(~0u, mx, o));
    float e[4], s = 0.f;
#pragma unroll
    for (int q = 0; q < 4; ++q) { int c = lane + 32 * q; e[q] = (c < C_CLASSES) ? __expf(v[q] - mx) : 0.f; s += e[q]; }
#pragma unroll
    for (int o = 16; o; o >>= 1) s += __shfl_xor_sync(~0u, s, o);
    float scale = tw[row >> 6] / s;
#pragma unroll
    for (int q = 0; q < 4; ++q) {
        int c = lane + 32 * q;
        if (c < C_CLASSES) g_m[(size_t)c * NTN + row] = __float2bfloat16(e[q] * scale);
    }
}

// ============ GEMM1 + sigmoid + leaf product fused ============
// CTA 128(M batch) x 256(N = 4 trees). grid (64, 16). 512 threads = 16 warps (4m x 4n), warp 32x64.
// 4-stage cp.async ring, one barrier per segment.
#define G1_SOFF 2048
#define G1_ABUF 16384
#define G1_STG  49152                       // A 16KB + B 32KB
#define G1_SMEM (G1_SOFF + 4 * G1_STG)      // 198656

__global__ void __launch_bounds__(512) gemm1_kernel(const float* __restrict__ bias) {
    extern __shared__ char smem[];
    const uint32_t sb = s2u(smem);
    const int tid = threadIdx.x, wid = tid >> 5, lane = tid & 31;
    const int b0 = blockIdx.x * 128, ntb = blockIdx.y;

    if (tid < 252) {
        int tt = tid / 63, n = tid % 63;
        ((float*)(smem + 128))[tt * 64 + n] = bias[(ntb * 4 + tt) * N_NODES + n];
    }

    const char* xh = (const char*)g_xh + (size_t)b0 * 1024;
    const char* xl = (const char*)g_xl + (size_t)b0 * 1024;
    const char* wh = (const char*)g_wh + (size_t)(ntb * 256) * 1024;
    const char* wl = (const char*)g_wl + (size_t)(ntb * 256) * 1024;
    const char* Asrc[3] = {xh, xl, xh};
    const char* Bsrc[3] = {wh, wh, wl};

    // staging: A 1024 units (2/thread), B 2048 units (4/thread)
#define G1_SEG(seg) do { int _p = (seg) >> 3, _kc = (seg) & 7; \
    const char* _as = Asrc[_p] + _kc * 128; const char* _bs = Bsrc[_p] + _kc * 128; \
    uint32_t _d = sb + G1_SOFF + ((seg) & 3) * G1_STG; \
    _Pragma("unroll") for (int _i = 0; _i < 2; ++_i) { \
        int _u = tid + _i * 512, _r = _u >> 3, _cu = _u & 7; \
        cp16(_d + (uint32_t)(((_r << 3) + (_cu ^ (_r & 7))) << 4), _as + (size_t)_r * 1024 + (_cu << 4)); } \
    _Pragma("unroll") for (int _i = 0; _i < 4; ++_i) { \
        int _u = tid + _i * 512, _r = _u >> 3, _cu = _u & 7; \
        cp16(_d + G1_ABUF + (uint32_t)(((_r << 3) + (_cu ^ (_r & 7))) << 4), _bs + (size_t)_r * 1024 + (_cu << 4)); } \
    CP_COMMIT(); } while (0)

    // per-warp MMA geometry: warp tile 32(m) x 64(n)
    const int wm = wid & 3, wn = wid >> 2;
    const int m0w = wm * 32, n0w = wn * 64;
    const uint32_t sx = lane & 7;
    const uint32_t aKh = (lane >> 4) & 1, bKh = (lane >> 3) & 1;
    uint32_t rA[2], rB[4];
#pragma unroll
    for (int mt = 0; mt < 2; ++mt) rA[mt] = (uint32_t)(m0w + mt * 16 + (lane & 15)) * 128;
#pragma unroll
    for (int np = 0; np < 4; ++np)
        rB[np] = (uint32_t)(n0w + np * 16 + (lane & 7) + ((lane & 16) >> 1)) * 128;

    float acc[2][8][4];
#pragma unroll
    for (int mt = 0; mt < 2; ++mt)
#pragma unroll
        for (int nf = 0; nf < 8; ++nf)
#pragma unroll
            for (int q = 0; q < 4; ++q) acc[mt][nf][q] = 0.f;

    G1_SEG(0); G1_SEG(1); G1_SEG(2);
#pragma unroll 1
    for (int seg = 0; seg < 24; ++seg) {
        if (seg <= 21) { CP_WAIT(2); } else if (seg == 22) { CP_WAIT(1); } else { CP_WAIT(0); }
        __syncthreads();
        if (seg + 3 < 24) G1_SEG(seg + 3);   // slot (seg+3)&3: consumers done before barrier

        const uint32_t Ab = sb + G1_SOFF + (seg & 3) * G1_STG;
        const uint32_t Bb = Ab + G1_ABUF;
#pragma unroll
        for (int ks = 0; ks < 4; ++ks) {
            uint32_t a[2][4], b[4][4];
            const uint32_t koA = (((uint32_t)ks * 2 + aKh) ^ sx) << 4;
            const uint32_t koB = (((uint32_t)ks * 2 + bKh) ^ sx) << 4;
            LDSM4(a[0], Ab + rA[0] + koA);
            LDSM4(a[1], Ab + rA[1] + koA);
#pragma unroll
            for (int np = 0; np < 4; ++np) LDSM4(b[np], Bb + rB[np] + koB);
#pragma unroll
            for (int mt = 0; mt < 2; ++mt)
#pragma unroll
                for (int np = 0; np < 4; ++np) {
                    MMA(acc[mt][np * 2],     a[mt], b[np][0], b[np][1]);
                    MMA(acc[mt][np * 2 + 1], a[mt], b[np][2], b[np][3]);
                }
        }
    }
    __syncthreads();

    // ---- epilogue: acc -> dec smem (pitch 257 f32, overlays dead stage buffers) ----
    float* dec = (float*)(smem + G1_SOFF);
    {
        const int r4 = lane >> 2, c2 = (lane & 3) * 2;
#pragma unroll
        for (int mt = 0; mt < 2; ++mt)
#pragma unroll
            for (int nf = 0; nf < 8; ++nf) {
                int row = m0w + mt * 16 + r4, col = n0w + nf * 8 + c2;
                dec[row * 257 + col]           = acc[mt][nf][0];
                dec[row * 257 + col + 1]       = acc[mt][nf][1];
                dec[(row + 8) * 257 + col]     = acc[mt][nf][2];
                dec[(row + 8) * 257 + col + 1] = acc[mt][nf][3];
            }
    }
    __syncthreads();

    // per-thread: one (row, tree): sigmoid + leaf product + bf16 store
    {
        const int row = tid & 127, tree = tid >> 7;   // 128 rows x 4 trees = 512
        const float* dr = dec + row * 257 + tree * 64;
        const float* bs = ((const float*)(smem + 128)) + tree * 64;
        float dc[63];
#pragma unroll
        for (int n = 0; n < 63; ++n)
            dc[n] = __fdividef(1.f, 1.f + __expf(-(dr[n] + bs[n])));
        float p[64];
        p[0] = 1.f;
#pragma unroll
        for (int d = 0; d < 6; ++d)
#pragma unroll
            for (int i = (1 << d) - 1; i >= 0; --i) {
                float v = dc[(1 << d) - 1 + i], pi = p[i];
                p[2 * i + 1] = pi * v;
                p[2 * i]     = pi * (1.f - v);
            }
        __nv_bfloat16 ob[64];
#pragma unroll
        for (int l = 0; l < 64; ++l) ob[l] = __float2bfloat16(p[l]);
        uint4* dst = (uint4*)(g_lp + (size_t)(b0 + row) * NTN + ntb * 256 + tree * 64);
        const uint4* srcv = (const uint4*)ob;
#pragma unroll
        for (int q = 0; q < 8; ++q) dst[q] = srcv[q];
    }
}

// ============ GEMM2: partial[sl] = lp[:, sl*1024:+1024] @ M^T ============
// grid (128, 4): 64 batch rows x 128 classes x K-slice 1024. 8 warps (2m x 4n), warp 32x32.
#define G2_SOFF 1024
#define G2_BUF  24576                       // A 8KB + B 16KB
#define G2_SMEM (G2_SOFF + 2 * G2_BUF)      // 50176

__global__ void __launch_bounds__(256) gemm2_kernel() {
    extern __shared__ char smem[];
    const uint32_t sb = s2u(smem);
    const int tid = threadIdx.x, wid = tid >> 5, lane = tid & 31;
    const int b0 = blockIdx.x * 64, sl = blockIdx.y;

    const char* Ag = (const char*)g_lp + (size_t)b0 * 8192 + (size_t)sl * 2048;
    const char* Bg = (const char*)g_m + (size_t)sl * 2048;

#define G2_SEG(seg) do { uint32_t _b = sb + G2_SOFF + ((seg) & 1) * G2_BUF; \
    stage_tile(_b, Ag + (size_t)(seg) * 128, 8192, 64); \
    stage_tile(_b + 8192, Bg + (size_t)(seg) * 128, 8192, 128); \
    CP_COMMIT(); } while (0)

    const int wm = wid >> 2, wn = wid & 3;
    const int m0w = wm * 32, n0w = wn * 32;
    const uint32_t sx = lane & 7;
    const uint32_t aKh = (lane >> 4) & 1, bKh = (lane >> 3) & 1;
    uint32_t rA[2], rB[4];
#pragma unroll
    for (int mt = 0; mt < 2; ++mt) rA[mt] = (uint32_t)(m0w + mt * 16 + (lane & 15)) * 128;
#pragma unroll
    for (int nt = 0; nt < 4; ++nt) rB[nt] = (uint32_t)(n0w + nt * 8 + (lane & 7)) * 128;

    float acc[2][4][4];
#pragma unroll
    for (int mt = 0; mt < 2; ++mt)
#pragma unroll
        for (int nt = 0; nt < 4; ++nt)
#pragma unroll
            for (int q = 0; q < 4; ++q) acc[mt][nt][q] = 0.f;

    G2_SEG(0); G2_SEG(1);
#pragma unroll 1
    for (int seg = 0; seg < 16; ++seg) {
        if (seg < 15) { CP_WAIT(1); } else { CP_WAIT(0); }
        __syncthreads();
        uint32_t Ab = sb + G2_SOFF + (seg & 1) * G2_BUF;
        uint32_t Bb = Ab + 8192;
#pragma unroll
        for (int ks = 0; ks < 4; ++ks) {
            uint32_t a[2][4], b[4][2];
#pragma unroll
            for (int mt = 0; mt < 2; ++mt)
                LDSM4(a[mt], Ab + rA[mt] + ((((uint32_t)ks * 2 + aKh) ^ sx) << 4));
#pragma unroll
            for (int nt = 0; nt < 4; ++nt)
                LDSM2(b[nt], Bb + rB[nt] + ((((uint32_t)ks * 2 + bKh) ^ sx) << 4));
#pragma unroll
            for (int mt = 0; mt < 2; ++mt)
#pragma unroll
                for (int nt = 0; nt < 4; ++nt)
                    MMA(acc[mt][nt], a[mt], b[nt][0], b[nt][1]);
        }
        __syncthreads();
        if (seg + 2 < 16) G2_SEG(seg + 2);
    }

    {
        float* po = g_part + (size_t)sl * (B_TOT * C_CLASSES);
        const int r = lane >> 2, c2 = (lane & 3) * 2;
#pragma unroll
        for (int mt = 0; mt < 2; ++mt)
#pragma unroll
            for (int nt = 0; nt < 4; ++nt) {
                int row = b0 + m0w + mt * 16 + r;
                int col = n0w + nt * 8 + c2;
                if (col < C_CLASSES) {
                    po[(size_t)row * C_CLASSES + col]       = acc[mt][nt][0];
                    po[(size_t)(row + 8) * C_CLASSES + col] = acc[mt][nt][2];
                }
                if (col + 1 < C_CLASSES) {
                    po[(size_t)row * C_CLASSES + col + 1]       = acc[mt][nt][1];
                    po[(size_t)(row + 8) * C_CLASSES + col + 1] = acc[mt][nt][3];
                }
            }
    }
}

// ============ deterministic slice reduce ============
__global__ void reduce_kernel(float* __restrict__ out) {
    const int N = B_TOT * C_CLASSES;
    int i = blockIdx.x * 256 + threadIdx.x;
    if (i < N)
        out[i] = g_part[i] + g_part[i + N] + g_part[i + 2 * N] + g_part[i + 3 * N];
}

// ============ launch ============
extern "C" void kernel_launch(void* const* d_in, const int* in_sizes, int n_in,
                              void* d_out, int out_size) {
    const float* x    = (const float*)d_in[0];
    const float* W    = (const float*)d_in[1];
    const float* bias = (const float*)d_in[2];
    const float* ll   = (const float*)d_in[3];
    const float* tw   = (const float*)d_in[4];
    float* out = (float*)d_out;

    cudaFuncSetAttribute(gemm1_kernel, cudaFuncAttributeMaxDynamicSharedMemorySize, G1_SMEM);
    cudaFuncSetAttribute(gemm2_kernel, cudaFuncAttributeMaxDynamicSharedMemorySize, G2_SMEM);

    prep_x<<<B_TOT * D_DIM / 256, 256>>>(x);
    prep_w<<<NTN * D_DIM / 256, 256>>>(W);
    prep_m<<<512, 256>>>(ll, tw);
    gemm1_kernel<<<dim3(64, 16), 512, G1_SMEM>>>(bias);
    gemm2_kernel<<<dim3(128, 4), 256, G2_SMEM>>>();
    const int N = B_TOT * C_CLASSES;
    reduce_kernel<<<(N + 255) / 256, 256>>>(out);
}

// round 7
// speedup vs baseline: 1.1158x; 1.0956x over previous
#include <cuda_runtime.h>
#include <cuda_bf16.h>
#include <cstdint>

#define N_NODES 63
#define C_CLASSES 100
#define B_TOT 8192
#define D_DIM 512
#define NTN 4096

// ---------------- device scratch ----------------
__device__ __nv_bfloat16 g_xh[B_TOT * D_DIM], g_xl[B_TOT * D_DIM];
__device__ __nv_bfloat16 g_wh[NTN * D_DIM], g_wl[NTN * D_DIM];
__device__ __nv_bfloat16 g_m[128 * NTN];                    // rows >=100 stay zero
__device__ __nv_bfloat16 g_lp[(size_t)B_TOT * NTN];
__device__ float g_part[4 * B_TOT * C_CLASSES];

// ---------------- helpers ----------------
__device__ __forceinline__ uint32_t s2u(const void* p) {
    uint32_t a;
    asm("{ .reg .u64 t; cvta.to.shared.u64 t, %1; cvt.u32.u64 %0, t; }" : "=r"(a) : "l"(p));
    return a;
}
#define CP_COMMIT() asm volatile("cp.async.commit_group;" ::: "memory")
#define CP_WAIT(n)  asm volatile("cp.async.wait_group %0;" :: "n"(n) : "memory")
__device__ __forceinline__ void cp16(uint32_t dst, const void* src) {
    asm volatile("cp.async.cg.shared.global [%0], [%1], 16;" :: "r"(dst), "l"(src) : "memory");
}
// generic staged tile (gemm2): 256 threads
__device__ __forceinline__ void stage_tile(uint32_t dstBase, const char* src, size_t rowB, int nRows) {
    const int units = nRows * 8;
    for (int u = threadIdx.x; u < units; u += 256) {
        int r = u >> 3, cu = u & 7;
        cp16(dstBase + (uint32_t)(((r << 3) + (cu ^ (r & 7))) << 4), src + (size_t)r * rowB + (cu << 4));
    }
}

#define LDSM4(a, addr) asm volatile( \
    "ldmatrix.sync.aligned.m8n8.x4.shared.b16 {%0,%1,%2,%3}, [%4];" \
    : "=r"((a)[0]), "=r"((a)[1]), "=r"((a)[2]), "=r"((a)[3]) : "r"(addr))
#define LDSM2(b, addr) asm volatile( \
    "ldmatrix.sync.aligned.m8n8.x2.shared.b16 {%0,%1}, [%2];" \
    : "=r"((b)[0]), "=r"((b)[1]) : "r"(addr))
#define MMA(c, a, b0, b1) asm volatile( \
    "mma.sync.aligned.m16n8k16.row.col.f32.bf16.bf16.f32 " \
    "{%0,%1,%2,%3},{%4,%5,%6,%7},{%8,%9},{%0,%1,%2,%3};" \
    : "+f"((c)[0]), "+f"((c)[1]), "+f"((c)[2]), "+f"((c)[3]) \
    : "r"((a)[0]), "r"((a)[1]), "r"((a)[2]), "r"((a)[3]), "r"(b0), "r"(b1))

// ============ prep ============
__global__ void prep_x(const float* __restrict__ x) {
    int i = blockIdx.x * 256 + threadIdx.x;
    float v = x[i];
    __nv_bfloat16 h = __float2bfloat16(v);
    g_xh[i] = h;
    g_xl[i] = __float2bfloat16(v - __bfloat162float(h));
}
__global__ void prep_w(const float* __restrict__ W) {
    int i = blockIdx.x * 256 + threadIdx.x;
    int row = i >> 9, k = i & 511, t = row >> 6, n = row & 63;
    float v = (n < N_NODES) ? W[((size_t)t * N_NODES + n) * D_DIM + k] : 0.f;
    __nv_bfloat16 h = __float2bfloat16(v);
    g_wh[i] = h;
    g_wl[i] = __float2bfloat16(v - __bfloat162float(h));
}
__global__ void prep_m(const float* __restrict__ ll, const float* __restrict__ tw) {
    int row = blockIdx.x * 8 + (threadIdx.x >> 5);   // t*64 + l
    int lane = threadIdx.x & 31;
    const float* src = ll + (size_t)row * C_CLASSES;
    float v[4];
#pragma unroll
    for (int q = 0; q < 4; ++q) { int c = lane + 32 * q; v[q] = (c < C_CLASSES) ? src[c] : -1e30f; }
    float mx = fmaxf(fmaxf(v[0], v[1]), fmaxf(v[2], v[3]));
#pragma unroll
    for (int o = 16; o; o >>= 1) mx = fmaxf(mx, __shfl_xor_sync(~0u, mx, o));
    float e[4], s = 0.f;
#pragma unroll
    for (int q = 0; q < 4; ++q) { int c = lane + 32 * q; e[q] = (c < C_CLASSES) ? __expf(v[q] - mx) : 0.f; s += e[q]; }
#pragma unroll
    for (int o = 16; o; o >>= 1) s += __shfl_xor_sync(~0u, s, o);
    float scale = tw[row >> 6] / s;
#pragma unroll
    for (int q = 0; q < 4; ++q) {
        int c = lane + 32 * q;
        if (c < C_CLASSES) g_m[(size_t)c * NTN + row] = __float2bfloat16(e[q] * scale);
    }
}

// ============ GEMM1 + sigmoid + leaf product fused ============
// CTA 128(M) x 128(N = 2 trees). grid (64, 32). 512 threads = 16 warps (4m x 4n), warp 32x32.
// 2-stage ring, one barrier per segment, 2 CTAs per SM (launch_bounds(512,2)).
#define G1_SOFF 1024
#define G1_STG  32768                       // A 16KB + B 16KB
#define G1_SMEM (G1_SOFF + 2 * G1_STG)      // 66560

__global__ void __launch_bounds__(512, 2) gemm1_kernel(const float* __restrict__ bias) {
    extern __shared__ char smem[];
    const uint32_t sb = s2u(smem);
    const int tid = threadIdx.x, wid = tid >> 5, lane = tid & 31;
    const int b0 = blockIdx.x * 128, ntb = blockIdx.y;

    if (tid < 126) {
        int tt = tid / 63, n = tid % 63;
        ((float*)(smem + 128))[tt * 64 + n] = bias[(ntb * 2 + tt) * N_NODES + n];
    }

    // per-thread staging geometry: 2 A units + 2 B units (same shape)
    uint32_t dstOff[2];
    const char* srcXh;  const char* srcXl;  const char* srcWh;  const char* srcWl;
    {
        int u0 = tid, u1 = tid + 512;
        int r0 = u0 >> 3, c0 = u0 & 7, r1 = u1 >> 3, c1 = u1 & 7;
        dstOff[0] = (uint32_t)(((r0 << 3) + (c0 ^ (r0 & 7))) << 4);
        dstOff[1] = (uint32_t)(((r1 << 3) + (c1 ^ (r1 & 7))) << 4);
        // per-thread source byte offsets (same for unit0/1 pattern below)
        srcXh = (const char*)g_xh + (size_t)b0 * 1024;
        srcXl = (const char*)g_xl + (size_t)b0 * 1024;
        srcWh = (const char*)g_wh + (size_t)(ntb * 128) * 1024;
        srcWl = (const char*)g_wl + (size_t)(ntb * 128) * 1024;
    }
    const int sr0 = tid >> 3, sc0 = tid & 7;
    const size_t so0 = (size_t)sr0 * 1024 + (sc0 << 4);
    const size_t so1 = (size_t)(sr0 + 64) * 1024 + (sc0 << 4);

#define G1_SEG(seg) do { int _p = (seg) >> 3, _kc = (seg) & 7; \
    const char* _as = ((_p == 1) ? srcXl : srcXh) + _kc * 128; \
    const char* _bs = ((_p == 2) ? srcWl : srcWh) + _kc * 128; \
    uint32_t _d = sb + G1_SOFF + ((seg) & 1) * G1_STG; \
    cp16(_d + dstOff[0], _as + so0); \
    cp16(_d + dstOff[1], _as + so1); \
    cp16(_d + 16384 + dstOff[0], _bs + so0); \
    cp16(_d + 16384 + dstOff[1], _bs + so1); \
    CP_COMMIT(); } while (0)

    // per-warp MMA geometry: warp tile 32(m) x 32(n)
    const int wm = wid & 3, wn = wid >> 2;
    const int m0w = wm * 32, n0w = wn * 32;
    const uint32_t sx = lane & 7;
    const uint32_t aKh = (lane >> 4) & 1, bKh = (lane >> 3) & 1;
    uint32_t rA[2], rB[2];
#pragma unroll
    for (int mt = 0; mt < 2; ++mt) rA[mt] = (uint32_t)(m0w + mt * 16 + (lane & 15)) * 128;
#pragma unroll
    for (int nt = 0; nt < 2; ++nt)
        rB[nt] = (uint32_t)(n0w + nt * 16 + (lane & 7) + ((lane & 16) >> 1)) * 128;

    float acc[2][4][4];
#pragma unroll
    for (int mt = 0; mt < 2; ++mt)
#pragma unroll
        for (int nf = 0; nf < 4; ++nf)
#pragma unroll
            for (int q = 0; q < 4; ++q) acc[mt][nf][q] = 0.f;

    G1_SEG(0);
#pragma unroll 1
    for (int seg = 0; seg < 24; ++seg) {
        CP_WAIT(0);
        __syncthreads();
        if (seg + 1 < 24) G1_SEG(seg + 1);   // other slot: its readers finished before the barrier

        const uint32_t Ab = sb + G1_SOFF + (seg & 1) * G1_STG;
        const uint32_t Bb = Ab + 16384;
#pragma unroll
        for (int ks = 0; ks < 4; ++ks) {
            uint32_t a[2][4], b[2][4];
            const uint32_t koA = (((uint32_t)ks * 2 + aKh) ^ sx) << 4;
            const uint32_t koB = (((uint32_t)ks * 2 + bKh) ^ sx) << 4;
            LDSM4(a[0], Ab + rA[0] + koA);
            LDSM4(a[1], Ab + rA[1] + koA);
            LDSM4(b[0], Bb + rB[0] + koB);
            LDSM4(b[1], Bb + rB[1] + koB);
#pragma unroll
            for (int mt = 0; mt < 2; ++mt)
#pragma unroll
                for (int nt = 0; nt < 2; ++nt) {
                    MMA(acc[mt][nt * 2],     a[mt], b[nt][0], b[nt][1]);
                    MMA(acc[mt][nt * 2 + 1], a[mt], b[nt][2], b[nt][3]);
                }
        }
    }

    // ---- epilogue: two 64-col halves (one tree each); dec overlays stage smem ----
    float* dec = (float*)(smem + G1_SOFF);        // 128 x pitch65 f32 = 33KB
    const float* bsm = (const float*)(smem + 128);
    const int r4 = lane >> 2, c2 = (lane & 3) * 2;

#pragma unroll 1
    for (int h = 0; h < 2; ++h) {
        __syncthreads();
        if ((wn >> 1) == h) {
            const int colb = (wn & 1) * 32;
#pragma unroll
            for (int mt = 0; mt < 2; ++mt)
#pragma unroll
                for (int nf = 0; nf < 4; ++nf) {
                    int row = m0w + mt * 16 + r4, col = colb + nf * 8 + c2;
                    dec[row * 65 + col]           = acc[mt][nf][0];
                    dec[row * 65 + col + 1]       = acc[mt][nf][1];
                    dec[(row + 8) * 65 + col]     = acc[mt][nf][2];
                    dec[(row + 8) * 65 + col + 1] = acc[mt][nf][3];
                }
        }
        __syncthreads();
        if (tid < 256) {
            const int row = tid & 127, hh = tid >> 7;   // subtree half
            const float* dr = dec + row * 65;
            const float* bs = bsm + h * 64;
            float dc[63];
#pragma unroll
            for (int n = 0; n < 63; ++n)
                dc[n] = __fdividef(1.f, 1.f + __expf(-(dr[n] + bs[n])));
            float p[32];
            p[0] = hh ? dc[0] : (1.f - dc[0]);
#pragma unroll
            for (int d = 1; d < 6; ++d)
#pragma unroll
                for (int i = (1 << (d - 1)) - 1; i >= 0; --i) {
                    float v = dc[(1 << d) - 1 + hh * (1 << (d - 1)) + i], pi = p[i];
                    p[2 * i + 1] = pi * v;
                    p[2 * i]     = pi * (1.f - v);
                }
            __nv_bfloat16 ob[32];
#pragma unroll
            for (int l = 0; l < 32; ++l) ob[l] = __float2bfloat16(p[l]);
            uint4* dst = (uint4*)(g_lp + (size_t)(b0 + row) * NTN + (ntb * 2 + h) * 64 + hh * 32);
            const uint4* srcv = (const uint4*)ob;
#pragma unroll
            for (int q = 0; q < 4; ++q) dst[q] = srcv[q];
        }
    }
}

// ============ GEMM2: partial[sl] = lp[:, sl*1024:+1024] @ M^T ============
// grid (128, 4): 64 batch rows x 128 classes x K-slice 1024. 8 warps (2m x 4n), warp 32x32.
#define G2_SOFF 1024
#define G2_BUF  24576                       // A 8KB + B 16KB
#define G2_SMEM (G2_SOFF + 2 * G2_BUF)      // 50176

__global__ void __launch_bounds__(256) gemm2_kernel() {
    extern __shared__ char smem[];
    const uint32_t sb = s2u(smem);
    const int tid = threadIdx.x, wid = tid >> 5, lane = tid & 31;
    const int b0 = blockIdx.x * 64, sl = blockIdx.y;

    const char* Ag = (const char*)g_lp + (size_t)b0 * 8192 + (size_t)sl * 2048;
    const char* Bg = (const char*)g_m + (size_t)sl * 2048;

#define G2_SEG(seg) do { uint32_t _b = sb + G2_SOFF + ((seg) & 1) * G2_BUF; \
    stage_tile(_b, Ag + (size_t)(seg) * 128, 8192, 64); \
    stage_tile(_b + 8192, Bg + (size_t)(seg) * 128, 8192, 128); \
    CP_COMMIT(); } while (0)

    const int wm = wid >> 2, wn = wid & 3;
    const int m0w = wm * 32, n0w = wn * 32;
    const uint32_t sx = lane & 7;
    const uint32_t aKh = (lane >> 4) & 1, bKh = (lane >> 3) & 1;
    uint32_t rA[2], rB[4];
#pragma unroll
    for (int mt = 0; mt < 2; ++mt) rA[mt] = (uint32_t)(m0w + mt * 16 + (lane & 15)) * 128;
#pragma unroll
    for (int nt = 0; nt < 4; ++nt) rB[nt] = (uint32_t)(n0w + nt * 8 + (lane & 7)) * 128;

    float acc[2][4][4];
#pragma unroll
    for (int mt = 0; mt < 2; ++mt)
#pragma unroll
        for (int nt = 0; nt < 4; ++nt)
#pragma unroll
            for (int q = 0; q < 4; ++q) acc[mt][nt][q] = 0.f;

    G2_SEG(0); G2_SEG(1);
#pragma unroll 1
    for (int seg = 0; seg < 16; ++seg) {
        if (seg < 15) { CP_WAIT(1); } else { CP_WAIT(0); }
        __syncthreads();
        uint32_t Ab = sb + G2_SOFF + (seg & 1) * G2_BUF;
        uint32_t Bb = Ab + 8192;
#pragma unroll
        for (int ks = 0; ks < 4; ++ks) {
            uint32_t a[2][4], b[4][2];
#pragma unroll
            for (int mt = 0; mt < 2; ++mt)
                LDSM4(a[mt], Ab + rA[mt] + ((((uint32_t)ks * 2 + aKh) ^ sx) << 4));
#pragma unroll
            for (int nt = 0; nt < 4; ++nt)
                LDSM2(b[nt], Bb + rB[nt] + ((((uint32_t)ks * 2 + bKh) ^ sx) << 4));
#pragma unroll
            for (int mt = 0; mt < 2; ++mt)
#pragma unroll
                for (int nt = 0; nt < 4; ++nt)
                    MMA(acc[mt][nt], a[mt], b[nt][0], b[nt][1]);
        }
        __syncthreads();
        if (seg + 2 < 16) G2_SEG(seg + 2);
    }

    {
        float* po = g_part + (size_t)sl * (B_TOT * C_CLASSES);
        const int r = lane >> 2, c2 = (lane & 3) * 2;
#pragma unroll
        for (int mt = 0; mt < 2; ++mt)
#pragma unroll
            for (int nt = 0; nt < 4; ++nt) {
                int row = b0 + m0w + mt * 16 + r;
                int col = n0w + nt * 8 + c2;
                if (col < C_CLASSES) {
                    po[(size_t)row * C_CLASSES + col]       = acc[mt][nt][0];
                    po[(size_t)(row + 8) * C_CLASSES + col] = acc[mt][nt][2];
                }
                if (col + 1 < C_CLASSES) {
                    po[(size_t)row * C_CLASSES + col + 1]       = acc[mt][nt][1];
                    po[(size_t)(row + 8) * C_CLASSES + col + 1] = acc[mt][nt][3];
                }
            }
    }
}

// ============ deterministic slice reduce ============
__global__ void reduce_kernel(float* __restrict__ out) {
    const int N = B_TOT * C_CLASSES;
    int i = blockIdx.x * 256 + threadIdx.x;
    if (i < N)
        out[i] = g_part[i] + g_part[i + N] + g_part[i + 2 * N] + g_part[i + 3 * N];
}

// ============ launch ============
extern "C" void kernel_launch(void* const* d_in, const int* in_sizes, int n_in,
                              void* d_out, int out_size) {
    const float* x    = (const float*)d_in[0];
    const float* W    = (const float*)d_in[1];
    const float* bias = (const float*)d_in[2];
    const float* ll   = (const float*)d_in[3];
    const float* tw   = (const float*)d_in[4];
    float* out = (float*)d_out;

    cudaFuncSetAttribute(gemm1_kernel, cudaFuncAttributeMaxDynamicSharedMemorySize, G1_SMEM);
    cudaFuncSetAttribute(gemm2_kernel, cudaFuncAttributeMaxDynamicSharedMemorySize, G2_SMEM);

    prep_x<<<B_TOT * D_DIM / 256, 256>>>(x);
    prep_w<<<NTN * D_DIM / 256, 256>>>(W);
    prep_m<<<512, 256>>>(ll, tw);
    gemm1_kernel<<<dim3(64, 32), 512, G1_SMEM>>>(bias);
    gemm2_kernel<<<dim3(128, 4), 256, G2_SMEM>>>();
    const int N = B_TOT * C_CLASSES;
    reduce_kernel<<<(N + 255) / 256, 256>>>(out);
}